// round 3
// baseline (speedup 1.0000x reference)
#include <cuda_runtime.h>
#include <cuda_fp16.h>

#define BMAX 16384
__device__ float g_xp[BMAX * 512];
__device__ float g_hs[BMAX * 128];

__device__ __forceinline__ float fsig(float x) { return 1.0f / (1.0f + __expf(-x)); }
__device__ __forceinline__ float ftanh(float x) { return 2.0f * fsig(2.0f * x) - 1.0f; }
__device__ __forceinline__ unsigned pack2(float x, float y) {
    __half2 h = __floats2half2_rn(x, y);
    return *reinterpret_cast<unsigned*>(&h);
}
__device__ __forceinline__ void mma16816(float* c, const unsigned* a, unsigned b0, unsigned b1) {
    asm volatile(
        "mma.sync.aligned.m16n8k16.row.col.f32.f16.f16.f32 "
        "{%0,%1,%2,%3},{%4,%5,%6,%7},{%8,%9},{%0,%1,%2,%3};\n"
        : "+f"(c[0]), "+f"(c[1]), "+f"(c[2]), "+f"(c[3])
        : "r"(a[0]), "r"(a[1]), "r"(a[2]), "r"(a[3]), "r"(b0), "r"(b1));
}

// ---------------- encoder + input projection ----------------
__global__ void __launch_bounds__(128) enc_kernel(
    const float* __restrict__ img, const float* __restrict__ act,
    const float* __restrict__ c1w, const float* __restrict__ c1b,
    const float* __restrict__ c2w, const float* __restrict__ c2b,
    const float* __restrict__ encw, const float* __restrict__ encb,
    const float* __restrict__ wih, const float* __restrict__ bih,
    const float* __restrict__ bhh, int B)
{
    __shared__ float s_c1w[864], s_c1b[32];
    __shared__ float s_img[4][76], s_h1[4][800], s_h2[4][1600], s_x[4][136];

    int tid = threadIdx.x, lane = tid & 31, w = tid >> 5;
    int gi = blockIdx.x * 4 + w;
    bool valid = gi < B;

    for (int i = tid; i < 864; i += 128) s_c1w[i] = c1w[i];
    if (tid < 32) s_c1b[tid] = c1b[tid];
    if (valid) {
        for (int i = lane; i < 75; i += 32) s_img[w][i] = img[gi * 75 + i];
        if (lane < 8) s_x[w][128 + lane] = act[gi * 8 + lane];
    }
    __syncthreads();
    if (!valid) return;

    if (lane < 25) {
        int y = lane / 5, x = lane % 5;
        float p1[27];
        #pragma unroll
        for (int ic = 0; ic < 3; ic++)
            #pragma unroll
            for (int ky = 0; ky < 3; ky++)
                #pragma unroll
                for (int kx = 0; kx < 3; kx++) {
                    int yy = y + ky - 1, xx = x + kx - 1;
                    p1[ic*9+ky*3+kx] = (yy>=0 && yy<5 && xx>=0 && xx<5) ? s_img[w][ic*25+yy*5+xx] : 0.f;
                }
        #pragma unroll 4
        for (int oc = 0; oc < 32; oc++) {
            float a = s_c1b[oc];
            #pragma unroll
            for (int k = 0; k < 27; k++) a += p1[k] * s_c1w[oc*27+k];
            s_h1[w][oc*25+lane] = fmaxf(a, 0.f);
        }
    }
    __syncwarp();

    if (lane < 25) {
        float acc[64];
        #pragma unroll
        for (int oc = 0; oc < 64; oc++) acc[oc] = 0.f;
        int y = lane / 5, x = lane % 5;
        for (int ic = 0; ic < 32; ic++) {
            float p[9];
            #pragma unroll
            for (int ky = 0; ky < 3; ky++)
                #pragma unroll
                for (int kx = 0; kx < 3; kx++) {
                    int yy = y + ky - 1, xx = x + kx - 1;
                    p[ky*3+kx] = (yy>=0 && yy<5 && xx>=0 && xx<5) ? s_h1[w][ic*25+yy*5+xx] : 0.f;
                }
            #pragma unroll 8
            for (int oc = 0; oc < 64; oc++) {
                const float* wp = &c2w[(oc*32+ic)*9];
                float a = acc[oc];
                #pragma unroll
                for (int k = 0; k < 9; k++) a += p[k] * __ldg(wp + k);
                acc[oc] = a;
            }
        }
        #pragma unroll
        for (int oc = 0; oc < 64; oc++)
            s_h2[w][oc*25+lane] = fmaxf(acc[oc] + __ldg(&c2b[oc]), 0.f);
    }
    __syncwarp();

    { // z = h2 @ enc_w^T + enc_b
        float z[4];
        #pragma unroll
        for (int j = 0; j < 4; j++) z[j] = __ldg(&encb[lane + 32*j]);
        for (int k = 0; k < 1600; k += 4) {
            float4 hv = *reinterpret_cast<const float4*>(&s_h2[w][k]);
            #pragma unroll
            for (int j = 0; j < 4; j++) {
                float4 wv = __ldg(reinterpret_cast<const float4*>(&encw[(lane+32*j)*1600 + k]));
                z[j] += hv.x*wv.x + hv.y*wv.y + hv.z*wv.z + hv.w*wv.w;
            }
        }
        #pragma unroll
        for (int j = 0; j < 4; j++) s_x[w][lane + 32*j] = z[j];
    }
    __syncwarp();

    // xp = [z,action] @ w_ih^T + (b_ih + b_hh)
    for (int j = 0; j < 16; j++) {
        int r = lane + 32*j;
        float a = __ldg(&bih[r]) + __ldg(&bhh[r]);
        for (int k = 0; k < 136; k += 4) {
            float4 xv = *reinterpret_cast<const float4*>(&s_x[w][k]);
            float4 wv = __ldg(reinterpret_cast<const float4*>(&wih[r*136 + k]));
            a += xv.x*wv.x + xv.y*wv.y + xv.z*wv.z + xv.w*wv.w;
        }
        g_xp[gi*512 + r] = a;
    }
}

// ---------------- LSTM: 1 block, 8 warps, W_hh in mma fragments ----------------
__global__ void __launch_bounds__(256) lstm_kernel(
    const float* __restrict__ whh, float* __restrict__ d_out, int B, int out_size)
{
    __shared__ unsigned hbuf[2][64];
    int tid = threadIdx.x, lane = tid & 31, w = tid >> 5;
    int gr = lane >> 2, tg = lane & 3;

    unsigned a[4][8][4];
    #pragma unroll
    for (int t = 0; t < 4; t++) {
        int m0 = (t*8 + w) * 16;
        #pragma unroll
        for (int kt = 0; kt < 8; kt++) {
            int k0 = kt*16, r0 = m0+gr, r1 = m0+8+gr, c0 = k0+tg*2, c1 = c0+8;
            a[t][kt][0] = pack2(__ldg(&whh[r0*128+c0]), __ldg(&whh[r0*128+c0+1]));
            a[t][kt][1] = pack2(__ldg(&whh[r1*128+c0]), __ldg(&whh[r1*128+c0+1]));
            a[t][kt][2] = pack2(__ldg(&whh[r0*128+c1]), __ldg(&whh[r0*128+c1+1]));
            a[t][kt][3] = pack2(__ldg(&whh[r1*128+c1]), __ldg(&whh[r1*128+c1+1]));
        }
    }

    int r0 = w*16 + gr, r1 = r0 + 8;   // local h rows this thread produces
    if (tid < 64) hbuf[0][tid] = 0u;

    float cA = 0.f, cB = 0.f;
    float xpc[8], xpn[8];
    #pragma unroll
    for (int q = 0; q < 8; q++)
        xpc[q] = __ldg(&g_xp[(q>>1)*128 + ((q&1) ? r1 : r0)]);
    __syncthreads();

    for (int t = 0; t < B; t++) {
        if (t + 1 < B) {
            #pragma unroll
            for (int q = 0; q < 8; q++)
                xpn[q] = __ldg(&g_xp[(t+1)*512 + (q>>1)*128 + ((q&1) ? r1 : r0)]);
        }
        const unsigned* h2p = hbuf[t & 1];
        float acc[4][4];
        #pragma unroll
        for (int tt = 0; tt < 4; tt++) {
            acc[tt][0] = xpc[tt*2];   acc[tt][1] = 0.f;
            acc[tt][2] = xpc[tt*2+1]; acc[tt][3] = 0.f;
        }
        #pragma unroll
        for (int kt = 0; kt < 8; kt++) {
            unsigned b0 = h2p[kt*8 + tg];
            unsigned b1 = h2p[kt*8 + 4 + tg];
            #pragma unroll
            for (int tt = 0; tt < 4; tt++) mma16816(acc[tt], a[tt][kt], b0, b1);
        }
        // gates: i,f,g,o = tiles 0..3
        float i0 = fsig(acc[0][0]), f0 = fsig(acc[1][0]), g0 = ftanh(acc[2][0]), o0 = fsig(acc[3][0]);
        float i1 = fsig(acc[0][2]), f1 = fsig(acc[1][2]), g1 = ftanh(acc[2][2]), o1 = fsig(acc[3][2]);
        cA = f0*cA + i0*g0;
        cB = f1*cB + i1*g1;
        float h0 = o0*ftanh(cA), h1 = o1*ftanh(cB);

        if (tg == 0) {
            __half* hb = reinterpret_cast<__half*>(hbuf[(t+1) & 1]);
            hb[r0] = __float2half_rn(h0);
            hb[r1] = __float2half_rn(h1);
            g_hs[t*128 + r0] = h0;
            g_hs[t*128 + r1] = h1;
            if (t == B - 1) {
                d_out[out_size - 256 + r0] = h0;
                d_out[out_size - 256 + r1] = h1;
                d_out[out_size - 128 + r0] = cA;
                d_out[out_size - 128 + r1] = cB;
            }
        }
        __syncthreads();
        #pragma unroll
        for (int q = 0; q < 8; q++) xpc[q] = xpn[q];
    }
}

// ---------------- decoder ----------------
__global__ void __launch_bounds__(128) dec_kernel(
    const float* __restrict__ decw, const float* __restrict__ decb,
    const float* __restrict__ d1w, const float* __restrict__ d1b,
    const float* __restrict__ d2w, const float* __restrict__ d2b,
    float* __restrict__ out, int B)
{
    __shared__ float s_hs[4][128], s_d[4][1600], s_h[4][800], s_w2f[864];

    int tid = threadIdx.x, lane = tid & 31, w = tid >> 5;
    int gi = blockIdx.x * 4 + w;
    bool valid = gi < B;

    // flipped+transposed dct2 weights: s_w2f[ic*27 + oc*9 + k] = d2w[(ic*3+oc)*9 + (8-k)]
    for (int i = tid; i < 864; i += 128) {
        int ic = i / 27, rem = i % 27, oc = rem / 9, k = rem % 9;
        s_w2f[i] = d2w[(ic*3 + oc)*9 + (8 - k)];
    }
    if (valid)
        for (int i = lane; i < 128; i += 32) s_hs[w][i] = g_hs[gi*128 + i];
    __syncthreads();
    if (!valid) return;

    // dec linear: 1600 outputs
    for (int j = 0; j < 50; j++) {
        int o = lane + 32*j;
        float acc = __ldg(&decb[o]);
        for (int k = 0; k < 128; k += 4) {
            float4 hv = *reinterpret_cast<const float4*>(&s_hs[w][k]);
            float4 wv = __ldg(reinterpret_cast<const float4*>(&decw[o*128 + k]));
            acc += hv.x*wv.x + hv.y*wv.y + hv.z*wv.z + hv.w*wv.w;
        }
        s_d[w][o] = acc;
    }
    __syncwarp();

    // deconv1: 64->32, relu.  conv-equivalent weight: d1w[(ic*32+oc)*9 + (8-k)]
    if (lane < 25) {
        float acc[32];
        #pragma unroll
        for (int oc = 0; oc < 32; oc++) acc[oc] = 0.f;
        int y = lane / 5, x = lane % 5;
        for (int ic = 0; ic < 64; ic++) {
            float p[9];
            #pragma unroll
            for (int ky = 0; ky < 3; ky++)
                #pragma unroll
                for (int kx = 0; kx < 3; kx++) {
                    int yy = y + ky - 1, xx = x + kx - 1;
                    p[ky*3+kx] = (yy>=0 && yy<5 && xx>=0 && xx<5) ? s_d[w][ic*25+yy*5+xx] : 0.f;
                }
            const float* wp = &d1w[ic*32*9];
            #pragma unroll 8
            for (int oc = 0; oc < 32; oc++) {
                float a = acc[oc];
                #pragma unroll
                for (int k = 0; k < 9; k++) a += p[k] * __ldg(&wp[oc*9 + (8-k)]);
                acc[oc] = a;
            }
        }
        #pragma unroll
        for (int oc = 0; oc < 32; oc++)
            s_h[w][oc*25+lane] = fmaxf(acc[oc] + __ldg(&d1b[oc]), 0.f);
    }
    __syncwarp();

    // deconv2: 32->3, sigmoid
    if (lane < 25) {
        float acc[3] = {__ldg(&d2b[0]), __ldg(&d2b[1]), __ldg(&d2b[2])};
        int y = lane / 5, x = lane % 5;
        for (int ic = 0; ic < 32; ic++) {
            float p[9];
            #pragma unroll
            for (int ky = 0; ky < 3; ky++)
                #pragma unroll
                for (int kx = 0; kx < 3; kx++) {
                    int yy = y + ky - 1, xx = x + kx - 1;
                    p[ky*3+kx] = (yy>=0 && yy<5 && xx>=0 && xx<5) ? s_h[w][ic*25+yy*5+xx] : 0.f;
                }
            #pragma unroll
            for (int oc = 0; oc < 3; oc++) {
                float a = acc[oc];
                #pragma unroll
                for (int k = 0; k < 9; k++) a += p[k] * s_w2f[ic*27 + oc*9 + k];
                acc[oc] = a;
            }
        }
        #pragma unroll
        for (int oc = 0; oc < 3; oc++)
            out[gi*75 + oc*25 + lane] = fsig(acc[oc]);
    }
}

extern "C" void kernel_launch(void* const* d_in, const int* in_sizes, int n_in,
                              void* d_out, int out_size)
{
    const float* img   = (const float*)d_in[0];
    const float* act   = (const float*)d_in[1];
    const float* c1w   = (const float*)d_in[2];
    const float* c1b   = (const float*)d_in[3];
    const float* c2w   = (const float*)d_in[4];
    const float* c2b   = (const float*)d_in[5];
    const float* encw  = (const float*)d_in[6];
    const float* encb  = (const float*)d_in[7];
    const float* wih   = (const float*)d_in[8];
    const float* whh   = (const float*)d_in[9];
    const float* bih   = (const float*)d_in[10];
    const float* bhh   = (const float*)d_in[11];
    const float* decw  = (const float*)d_in[12];
    const float* decb  = (const float*)d_in[13];
    const float* d1w   = (const float*)d_in[14];
    const float* d1b   = (const float*)d_in[15];
    const float* d2w   = (const float*)d_in[16];
    const float* d2b   = (const float*)d_in[17];
    float* out = (float*)d_out;

    int B = in_sizes[0] / 75;
    int blocks = (B + 3) / 4;

    enc_kernel<<<blocks, 128>>>(img, act, c1w, c1b, c2w, c2b, encw, encb, wih, bih, bhh, B);
    lstm_kernel<<<1, 256>>>(whh, out, B, out_size);
    dec_kernel<<<blocks, 128>>>(decw, decb, d1w, d1b, d2w, d2b, out, B);
}

// round 4
// speedup vs baseline: 1.3165x; 1.3165x over previous
#include <cuda_runtime.h>
#include <cuda_fp16.h>

#define BMAX 16384
__device__ float g_xp[BMAX * 512];
__device__ float g_hs[BMAX * 128];

__device__ __forceinline__ float fsig(float x) { return 1.0f / (1.0f + __expf(-x)); }
__device__ __forceinline__ float ftanh(float x) { return 2.0f * fsig(2.0f * x) - 1.0f; }
__device__ __forceinline__ unsigned pack2(float x, float y) {
    __half2 h = __floats2half2_rn(x, y);
    return *reinterpret_cast<unsigned*>(&h);
}
__device__ __forceinline__ void mma16816(float* c, const unsigned* a, unsigned b0, unsigned b1) {
    asm volatile(
        "mma.sync.aligned.m16n8k16.row.col.f32.f16.f16.f32 "
        "{%0,%1,%2,%3},{%4,%5,%6,%7},{%8,%9},{%0,%1,%2,%3};\n"
        : "+f"(c[0]), "+f"(c[1]), "+f"(c[2]), "+f"(c[3])
        : "r"(a[0]), "r"(a[1]), "r"(a[2]), "r"(a[3]), "r"(b0), "r"(b1));
}

// ================= encoder + input projection =================
__global__ void __launch_bounds__(128) enc_kernel(
    const float* __restrict__ img, const float* __restrict__ act,
    const float* __restrict__ c1w, const float* __restrict__ c1b,
    const float* __restrict__ c2w, const float* __restrict__ c2b,
    const float* __restrict__ encw, const float* __restrict__ encb,
    const float* __restrict__ wih, const float* __restrict__ bih,
    const float* __restrict__ bhh, int B)
{
    __shared__ float s_img[4][76];
    __shared__ float s_x[4][136];     // [z(128) | action(8)]
    __shared__ float s_h2[4][1600];
    __shared__ float s_wt[4608];      // region: h1 (4x800) / weight tiles

    int tid = threadIdx.x, lane = tid & 31, w = tid >> 5;
    int gi = blockIdx.x * 4 + w;
    bool valid = gi < B;
    float* s_h1 = s_wt + w * 800;

    if (valid) {
        for (int i = lane; i < 75; i += 32) s_img[w][i] = img[gi * 75 + i];
        if (lane < 8) s_x[w][128 + lane] = act[gi * 8 + lane];
    }
    __syncwarp();

    // ---- conv1 (3->32) relu ----
    if (lane < 25) {
        int y = lane / 5, x = lane % 5;
        float p1[27];
        #pragma unroll
        for (int ic = 0; ic < 3; ic++)
            #pragma unroll
            for (int ky = 0; ky < 3; ky++)
                #pragma unroll
                for (int kx = 0; kx < 3; kx++) {
                    int yy = y + ky - 1, xx = x + kx - 1;
                    p1[ic*9+ky*3+kx] = (yy>=0 && yy<5 && xx>=0 && xx<5) ? s_img[w][ic*25+yy*5+xx] : 0.f;
                }
        #pragma unroll 4
        for (int oc = 0; oc < 32; oc++) {
            float a = __ldg(&c1b[oc]);
            #pragma unroll
            for (int k = 0; k < 27; k++) a += p1[k] * __ldg(&c1w[oc*27+k]);
            s_h1[oc*25+lane] = fmaxf(a, 0.f);
        }
    }
    __syncwarp();

    // ---- conv2 (32->64) relu ----
    if (lane < 25) {
        float acc[64];
        #pragma unroll
        for (int oc = 0; oc < 64; oc++) acc[oc] = 0.f;
        int y = lane / 5, x = lane % 5;
        for (int ic = 0; ic < 32; ic++) {
            float p[9];
            #pragma unroll
            for (int ky = 0; ky < 3; ky++)
                #pragma unroll
                for (int kx = 0; kx < 3; kx++) {
                    int yy = y + ky - 1, xx = x + kx - 1;
                    p[ky*3+kx] = (yy>=0 && yy<5 && xx>=0 && xx<5) ? s_h1[ic*25+yy*5+xx] : 0.f;
                }
            #pragma unroll 8
            for (int oc = 0; oc < 64; oc++) {
                const float* wp = &c2w[(oc*32+ic)*9];
                float a = acc[oc];
                #pragma unroll
                for (int k = 0; k < 9; k++) a += p[k] * __ldg(wp + k);
                acc[oc] = a;
            }
        }
        #pragma unroll
        for (int oc = 0; oc < 64; oc++)
            s_h2[w][oc*25+lane] = fmaxf(acc[oc] + __ldg(&c2b[oc]), 0.f);
    }
    __syncthreads();   // h1 region now reusable as tile buffer; h2 done

    // ---- enc linear: z = h2 @ enc_w^T + enc_b  (tiled, conflict-free pitch 132) ----
    for (int ot = 0; ot < 4; ot++) {
        float acc = 0.f;
        for (int kt = 0; kt < 13; kt++) {
            int k0 = kt * 128, klen = (kt == 12) ? 64 : 128;
            __syncthreads();
            for (int idx = tid; idx < 32 * klen; idx += 128) {
                int r = idx / klen, k = idx - r * klen;
                s_wt[r*132 + k] = encw[(ot*32 + r)*1600 + k0 + k];
            }
            __syncthreads();
            const float4* wt4 = reinterpret_cast<const float4*>(&s_wt[lane*132]);
            const float4* h4  = reinterpret_cast<const float4*>(&s_h2[w][k0]);
            int n4 = klen >> 2;
            #pragma unroll 8
            for (int q = 0; q < n4; q++) {
                float4 wv = wt4[q], hv = h4[q];
                acc += wv.x*hv.x + wv.y*hv.y + wv.z*hv.z + wv.w*hv.w;
            }
        }
        s_x[w][ot*32 + lane] = acc + __ldg(&encb[ot*32 + lane]);
    }

    // ---- xp = [z,action] @ w_ih^T + (b_ih+b_hh)  (tiled, pitch 144) ----
    for (int ot = 0; ot < 16; ot++) {
        __syncthreads();
        for (int idx = tid; idx < 32 * 136; idx += 128) {
            int r = idx / 136, k = idx - r * 136;
            s_wt[r*144 + k] = wih[(ot*32 + r)*136 + k];
        }
        __syncthreads();
        float acc = 0.f;
        const float4* wt4 = reinterpret_cast<const float4*>(&s_wt[lane*144]);
        const float4* xv4 = reinterpret_cast<const float4*>(&s_x[w][0]);
        #pragma unroll 17
        for (int q = 0; q < 34; q++) {
            float4 wv = wt4[q], xv = xv4[q];
            acc += wv.x*xv.x + wv.y*xv.y + wv.z*xv.z + wv.w*xv.w;
        }
        if (valid) {
            int o = ot*32 + lane;
            g_xp[gi*512 + o] = acc + __ldg(&bih[o]) + __ldg(&bhh[o]);
        }
    }
}

// ================= LSTM: 1 block, 16 warps, 2 tiles/warp =================
// warp w<8:  gates (i,g) for h-block w   -> produce s_u = sig(i)*tanh(g)
// warp w>=8: gates (f,o) for h-block w-8 -> own c, produce h
__global__ void __launch_bounds__(512) lstm_kernel(
    const float* __restrict__ whh, float* __restrict__ d_out, int B, int out_size)
{
    __shared__ unsigned hbuf[2][64];
    __shared__ float s_u[128];
    int tid = threadIdx.x, lane = tid & 31, w = tid >> 5;
    int gr = lane >> 2, tg = lane & 3;
    bool lo = (w < 8);
    int hb = lo ? w : w - 8;
    int t0 = (lo ? 0 : 8) + hb;     // i or f tile
    int t1 = (lo ? 16 : 24) + hb;   // g or o tile

    unsigned a[2][8][4];
    {
        int tiles[2] = {t0, t1};
        #pragma unroll
        for (int tt = 0; tt < 2; tt++) {
            int m0 = tiles[tt] * 16;
            #pragma unroll
            for (int kt = 0; kt < 8; kt++) {
                int k0 = kt*16, r0 = m0+gr, r1 = m0+8+gr, c0 = k0+tg*2, c1 = c0+8;
                a[tt][kt][0] = pack2(__ldg(&whh[r0*128+c0]), __ldg(&whh[r0*128+c0+1]));
                a[tt][kt][1] = pack2(__ldg(&whh[r1*128+c0]), __ldg(&whh[r1*128+c0+1]));
                a[tt][kt][2] = pack2(__ldg(&whh[r0*128+c1]), __ldg(&whh[r0*128+c1+1]));
                a[tt][kt][3] = pack2(__ldg(&whh[r1*128+c1]), __ldg(&whh[r1*128+c1+1]));
            }
        }
    }
    int rr0 = hb*16 + gr, rr1 = rr0 + 8;
    int xo0 = t0*16 + gr, xo1 = xo0 + 8, xo2 = t1*16 + gr, xo3 = xo2 + 8;
    if (tid < 64) hbuf[0][tid] = 0u;

    float cs = 0.f;   // hi warps, tg0: c[rr0]; tg1: c[rr1]
    float xc0=0,xc1=0,xc2=0,xc3=0, xn0=0,xn1=0,xn2=0,xn3=0;
    if (tg == 0) {
        xc0 = __ldg(&g_xp[xo0]); xc1 = __ldg(&g_xp[xo1]);
        xc2 = __ldg(&g_xp[xo2]); xc3 = __ldg(&g_xp[xo3]);
    }
    __syncthreads();

    for (int t = 0; t < B; t++) {
        if (tg == 0 && t + 1 < B) {
            const float* xp = &g_xp[(t+1) * 512];
            xn0 = __ldg(xp + xo0); xn1 = __ldg(xp + xo1);
            xn2 = __ldg(xp + xo2); xn3 = __ldg(xp + xo3);
        }
        float acc0[4], acc1[4];
        acc0[0] = (tg==0) ? xc0 : 0.f; acc0[1] = 0.f;
        acc0[2] = (tg==0) ? xc1 : 0.f; acc0[3] = 0.f;
        acc1[0] = (tg==0) ? xc2 : 0.f; acc1[1] = 0.f;
        acc1[2] = (tg==0) ? xc3 : 0.f; acc1[3] = 0.f;
        const unsigned* h2p = hbuf[t & 1];
        #pragma unroll
        for (int kt = 0; kt < 8; kt++) {
            unsigned b0 = h2p[kt*8 + tg], b1 = h2p[kt*8 + 4 + tg];
            mma16816(acc0, a[0][kt], b0, b1);
            mma16816(acc1, a[1][kt], b0, b1);
        }
        // distribute the 4 pre-activations of lane (gr,0) to lanes tg=0..3
        int src = lane & ~3;
        float d0 = __shfl_sync(0xffffffffu, acc0[0], src);
        float d1 = __shfl_sync(0xffffffffu, acc0[2], src);
        float d2 = __shfl_sync(0xffffffffu, acc1[0], src);
        float d3 = __shfl_sync(0xffffffffu, acc1[2], src);
        float pre = (tg==0) ? d0 : (tg==1) ? d1 : (tg==2) ? d2 : d3;
        float fo;
        if (lo) {
            // tg0:sig(i0) tg1:sig(i1) tg2:tanh(g0) tg3:tanh(g1) — branchless via sigmoid
            float s = fsig((tg < 2) ? pre : 2.f * pre);
            fo = (tg < 2) ? s : (2.f * s - 1.f);
            float other = __shfl_down_sync(0xffffffffu, fo, 2);
            if (tg < 2) s_u[(tg == 0) ? rr0 : rr1] = fo * other;
        } else {
            fo = fsig(pre);   // tg0:f0 tg1:f1 tg2:o0 tg3:o1
        }
        __syncthreads();      // s_u ready
        if (!lo) {
            float og = __shfl_down_sync(0xffffffffu, fo, 2);
            if (tg < 2) {
                int r = (tg == 0) ? rr0 : rr1;
                cs = fmaf(fo, cs, s_u[r]);
                float h = og * ftanh(cs);
                __half* hn = reinterpret_cast<__half*>(hbuf[(t+1) & 1]);
                hn[r] = __float2half_rn(h);
                g_hs[t*128 + r] = h;
                if (t == B - 1) {
                    d_out[out_size - 256 + r] = h;
                    d_out[out_size - 128 + r] = cs;
                }
            }
        }
        __syncthreads();      // hbuf ready
        xc0 = xn0; xc1 = xn1; xc2 = xn2; xc3 = xn3;
    }
}

// ================= decoder =================
__global__ void __launch_bounds__(128) dec_kernel(
    const float* __restrict__ decw, const float* __restrict__ decb,
    const float* __restrict__ d1w, const float* __restrict__ d1b,
    const float* __restrict__ d2w, const float* __restrict__ d2b,
    float* __restrict__ out, int B)
{
    __shared__ float s_hs[4][128];
    __shared__ float s_d[4][1600];
    __shared__ float s_wt[4224];     // region: weight tiles / deconv1 output (4x800)
    __shared__ float s_w2f[864];

    int tid = threadIdx.x, lane = tid & 31, w = tid >> 5;
    int gi = blockIdx.x * 4 + w;
    bool valid = gi < B;

    for (int i = tid; i < 864; i += 128) {
        int ic = i / 27, rem = i % 27, oc = rem / 9, k = rem % 9;
        s_w2f[i] = d2w[(ic*3 + oc)*9 + (8 - k)];
    }
    if (valid)
        for (int i = lane; i < 128; i += 32) s_hs[w][i] = g_hs[gi*128 + i];

    // ---- dec linear: tiled, pitch 132 ----
    for (int ot = 0; ot < 50; ot++) {
        __syncthreads();
        for (int idx = tid; idx < 4096; idx += 128) {
            int r = idx >> 7, k = idx & 127;
            s_wt[r*132 + k] = decw[(ot*32 + r)*128 + k];
        }
        __syncthreads();
        float acc = 0.f;
        const float4* wt4 = reinterpret_cast<const float4*>(&s_wt[lane*132]);
        const float4* h4  = reinterpret_cast<const float4*>(&s_hs[w][0]);
        #pragma unroll 8
        for (int q = 0; q < 32; q++) {
            float4 wv = wt4[q], hv = h4[q];
            acc += wv.x*hv.x + wv.y*hv.y + wv.z*hv.z + wv.w*hv.w;
        }
        s_d[w][ot*32 + lane] = acc + __ldg(&decb[ot*32 + lane]);
    }
    __syncthreads();   // tile region reusable for deconv1 output

    float* s_h1 = s_wt + w * 800;

    // ---- deconv1 (64->32) relu ----
    if (lane < 25) {
        float acc[32];
        #pragma unroll
        for (int oc = 0; oc < 32; oc++) acc[oc] = 0.f;
        int y = lane / 5, x = lane % 5;
        for (int ic = 0; ic < 64; ic++) {
            float p[9];
            #pragma unroll
            for (int ky = 0; ky < 3; ky++)
                #pragma unroll
                for (int kx = 0; kx < 3; kx++) {
                    int yy = y + ky - 1, xx = x + kx - 1;
                    p[ky*3+kx] = (yy>=0 && yy<5 && xx>=0 && xx<5) ? s_d[w][ic*25+yy*5+xx] : 0.f;
                }
            const float* wp = &d1w[ic*32*9];
            #pragma unroll 8
            for (int oc = 0; oc < 32; oc++) {
                float a = acc[oc];
                #pragma unroll
                for (int k = 0; k < 9; k++) a += p[k] * __ldg(&wp[oc*9 + (8-k)]);
                acc[oc] = a;
            }
        }
        #pragma unroll
        for (int oc = 0; oc < 32; oc++)
            s_h1[oc*25+lane] = fmaxf(acc[oc] + __ldg(&d1b[oc]), 0.f);
    }
    __syncwarp();

    // ---- deconv2 (32->3) sigmoid ----
    if (valid && lane < 25) {
        float acc[3] = {__ldg(&d2b[0]), __ldg(&d2b[1]), __ldg(&d2b[2])};
        int y = lane / 5, x = lane % 5;
        for (int ic = 0; ic < 32; ic++) {
            float p[9];
            #pragma unroll
            for (int ky = 0; ky < 3; ky++)
                #pragma unroll
                for (int kx = 0; kx < 3; kx++) {
                    int yy = y + ky - 1, xx = x + kx - 1;
                    p[ky*3+kx] = (yy>=0 && yy<5 && xx>=0 && xx<5) ? s_h1[ic*25+yy*5+xx] : 0.f;
                }
            #pragma unroll
            for (int oc = 0; oc < 3; oc++) {
                float a = acc[oc];
                #pragma unroll
                for (int k = 0; k < 9; k++) a += p[k] * s_w2f[ic*27 + oc*9 + k];
                acc[oc] = a;
            }
        }
        #pragma unroll
        for (int oc = 0; oc < 3; oc++)
            out[gi*75 + oc*25 + lane] = fsig(acc[oc]);
    }
}

extern "C" void kernel_launch(void* const* d_in, const int* in_sizes, int n_in,
                              void* d_out, int out_size)
{
    const float* img   = (const float*)d_in[0];
    const float* act   = (const float*)d_in[1];
    const float* c1w   = (const float*)d_in[2];
    const float* c1b   = (const float*)d_in[3];
    const float* c2w   = (const float*)d_in[4];
    const float* c2b   = (const float*)d_in[5];
    const float* encw  = (const float*)d_in[6];
    const float* encb  = (const float*)d_in[7];
    const float* wih   = (const float*)d_in[8];
    const float* whh   = (const float*)d_in[9];
    const float* bih   = (const float*)d_in[10];
    const float* bhh   = (const float*)d_in[11];
    const float* decw  = (const float*)d_in[12];
    const float* decb  = (const float*)d_in[13];
    const float* d1w   = (const float*)d_in[14];
    const float* d1b   = (const float*)d_in[15];
    const float* d2w   = (const float*)d_in[16];
    const float* d2b   = (const float*)d_in[17];
    float* out = (float*)d_out;

    int B = in_sizes[0] / 75;
    int blocks = (B + 3) / 4;

    enc_kernel<<<blocks, 128>>>(img, act, c1w, c1b, c2w, c2b, encw, encb, wih, bih, bhh, B);
    lstm_kernel<<<1, 512>>>(whh, out, B, out_size);
    dec_kernel<<<blocks, 128>>>(decw, decb, d1w, d1b, d2w, d2b, out, B);
}